// round 3
// baseline (speedup 1.0000x reference)
#include <cuda_runtime.h>
#include <cuda_fp16.h>
#include <math.h>

#define NN 100000
#define EE 1600000
#define HC 64
#define IN_DIM 128

typedef unsigned long long ull;

// ---------------- scratch (device globals, allocation-free) ----------------
static __device__ __half2 g_xph[(size_t)NN * 32];  // xp [N,64] as fp16 (half2 pairs)
static __device__ float4  g_as4[NN];               // a_src [N,4]
static __device__ float4  g_dpk[2 * NN];           // [2d]=a_dst, [2d+1]=rcp*exp(-m)
static __device__ int     g_cnt[NN];               // degree histogram
static __device__ int2    g_fc[NN];                // {row start, fill cursor}
static __device__ int     g_rowptr[NN + 1];        // CSR row pointers
static __device__ int     g_bsum[512];             // scan partials
static __device__ int     g_boff[512];             // scan offsets
static __device__ int     g_csr_src[EE];           // CSR src ids

__device__ __forceinline__ float lrelu(float v) { return v >= 0.f ? v : 0.2f * v; }

__device__ __forceinline__ ull fma2(ull a, ull b, ull c) {
    ull d;
    asm("fma.rn.f32x2 %0, %1, %2, %3;" : "=l"(d) : "l"(a), "l"(b), "l"(c));
    return d;
}
__device__ __forceinline__ float2 upk(ull u) {
    float2 f;
    asm("mov.b64 {%0, %1}, %2;" : "=f"(f.x), "=f"(f.y) : "l"(u));
    return f;
}

// ---------------- init: zero histogram ----------------
__global__ void init_kernel(int n) {
    int i = blockIdx.x * blockDim.x + threadIdx.x;
    if (i < n) g_cnt[i] = 0;
}

// ---------------- GEMM: xp = x @ W (f32x2 packed over k) + attn epilogue ----------------
// 64x64 tile, 256 threads, 4x4 per thread, K split in 2 halves of 64.
__global__ __launch_bounds__(256) void gemm_kernel(
    const float* __restrict__ x, const float* __restrict__ W,
    const float* __restrict__ att_src, const float* __restrict__ att_dst, int n)
{
    __shared__ float  xs[64 * 68];        // [row][k] stride 68
    __shared__ float2 ws2[32 * 64];       // [k2][col] packed (w[2k2],w[2k2+1])
    int tid = threadIdx.x;
    int tx = tid & 15, ty = tid >> 4;
    int r0 = blockIdx.x * 64;

    ull acc2[4][4];
#pragma unroll
    for (int a = 0; a < 4; a++)
#pragma unroll
        for (int b = 0; b < 4; b++) acc2[a][b] = 0ull;

    for (int kh = 0; kh < 2; kh++) {
        // stage x tile [row][k]
#pragma unroll
        for (int q = 0; q < 4; q++) {
            int idx = tid + q * 256;          // 0..1023
            int row = idx >> 4;
            int k4  = idx & 15;
            float4 v = make_float4(0.f, 0.f, 0.f, 0.f);
            int grow = r0 + row;
            if (grow < n)
                v = *(const float4*)(x + (size_t)grow * IN_DIM + kh * 64 + k4 * 4);
            *(float4*)(xs + row * 68 + k4 * 4) = v;
        }
        // stage W packed over k pairs: ws2[k2][c]
#pragma unroll
        for (int q = 0; q < 8; q++) {
            int idx = tid + q * 256;          // 0..2047
            int k2 = idx >> 6;                // 0..31
            int c  = idx & 63;
            int k  = kh * 64 + 2 * k2;
            ws2[k2 * 64 + c] = make_float2(W[(size_t)k * HC + c], W[(size_t)(k + 1) * HC + c]);
        }
        __syncthreads();
#pragma unroll 8
        for (int k2 = 0; k2 < 32; k2++) {
            const ull* wp = (const ull*)(ws2 + k2 * 64 + 4 * tx);
            ull w0 = wp[0], w1 = wp[1], w2 = wp[2], w3 = wp[3];
#pragma unroll
            for (int r = 0; r < 4; r++) {
                ull xv = *(const ull*)(xs + (ty * 4 + r) * 68 + 2 * k2);
                acc2[r][0] = fma2(xv, w0, acc2[r][0]);
                acc2[r][1] = fma2(xv, w1, acc2[r][1]);
                acc2[r][2] = fma2(xv, w2, acc2[r][2]);
                acc2[r][3] = fma2(xv, w3, acc2[r][3]);
            }
        }
        __syncthreads();
    }

    float4 asv = __ldg((const float4*)(att_src + 4 * tx));
    float4 adv = __ldg((const float4*)(att_dst + 4 * tx));
    int h = tx >> 2;

#pragma unroll
    for (int r = 0; r < 4; r++) {
        float2 p0 = upk(acc2[r][0]);
        float2 p1 = upk(acc2[r][1]);
        float2 p2 = upk(acc2[r][2]);
        float2 p3 = upk(acc2[r][3]);
        float a0 = p0.x + p0.y, a1 = p1.x + p1.y;
        float a2 = p2.x + p2.y, a3 = p3.x + p3.y;

        float asr = a0 * asv.x + a1 * asv.y + a2 * asv.z + a3 * asv.w;
        float adr = a0 * adv.x + a1 * adv.y + a2 * adv.z + a3 * adv.w;
        asr += __shfl_xor_sync(0xffffffffu, asr, 1);
        asr += __shfl_xor_sync(0xffffffffu, asr, 2);
        adr += __shfl_xor_sync(0xffffffffu, adr, 1);
        adr += __shfl_xor_sync(0xffffffffu, adr, 2);

        int row = r0 + ty * 4 + r;
        if (row < n) {
            if ((tx & 3) == 0) {
                ((float*)&g_as4[row])[h] = asr;
                ((float*)&g_dpk[2 * (size_t)row])[h] = adr;
            }
            __half2 h0 = __floats2half2_rn(a0, a1);
            __half2 h1 = __floats2half2_rn(a2, a3);
            uint2 pv;
            pv.x = *(unsigned*)&h0;
            pv.y = *(unsigned*)&h1;
            *(uint2*)(g_xph + (size_t)row * 32 + 2 * tx) = pv;
        }
    }
}

// ---------------- CSR build ----------------
__global__ void hist_kernel(const int* __restrict__ ei, int e) {
    int t = blockIdx.x * blockDim.x + threadIdx.x;
    int base = t * 4;
    if (base + 3 < e) {
        int4 d4 = *(const int4*)(ei + e + base);
        atomicAdd(&g_cnt[d4.x], 1);
        atomicAdd(&g_cnt[d4.y], 1);
        atomicAdd(&g_cnt[d4.z], 1);
        atomicAdd(&g_cnt[d4.w], 1);
    } else {
        for (int i = base; i < e; i++) atomicAdd(&g_cnt[ei[e + i]], 1);
    }
}

__global__ void scan1_kernel(int n) {
    __shared__ int sd[512];
    int t = threadIdx.x, i = blockIdx.x * 512 + t;
    int v = (i < n) ? g_cnt[i] : 0;
    sd[t] = v; __syncthreads();
    for (int off = 1; off < 512; off <<= 1) {
        int x = (t >= off) ? sd[t - off] : 0;
        __syncthreads();
        sd[t] += x;
        __syncthreads();
    }
    if (i < n) g_rowptr[i + 1] = sd[t];
    if (t == 511) g_bsum[blockIdx.x] = sd[511];
}

__global__ void scan2_kernel(int nb) {
    __shared__ int sd[512];
    int t = threadIdx.x;
    int v = (t < nb) ? g_bsum[t] : 0;
    sd[t] = v; __syncthreads();
    for (int off = 1; off < 512; off <<= 1) {
        int x = (t >= off) ? sd[t - off] : 0;
        __syncthreads();
        sd[t] += x;
        __syncthreads();
    }
    g_boff[t] = sd[t] - v;   // exclusive
}

// adds block offsets AND initializes fill cursors {start, 0}
__global__ void scan3_kernel(int n) {
    int t = threadIdx.x;
    int i = blockIdx.x * 512 + t;
    int inc = g_boff[blockIdx.x];
    int prev = 0;
    if (i < n && t > 0) prev = g_rowptr[i];     // scan1 value at i (pre-offset)
    __syncthreads();
    if (i < n) {
        g_rowptr[i + 1] += inc;
        g_fc[i] = make_int2(prev + inc, 0);
        if (i == 0) g_rowptr[0] = 0;
    }
}

__global__ void fill_kernel(const int* __restrict__ ei, int e) {
    int t = blockIdx.x * blockDim.x + threadIdx.x;
    if (t >= e) return;
    int s = ei[t], d = ei[e + t];
    int2* fc = &g_fc[d];
    int pos = atomicAdd(&fc->y, 1);
    g_csr_src[fc->x + pos] = s;
}

// ---------------- fused softmax + aggregation: one warp per dst node ----------------
__global__ __launch_bounds__(256) void aggregate_kernel(
    const float* __restrict__ bias, float* __restrict__ out, int n)
{
    __shared__ float sE[8][32][4];
    int w = (blockIdx.x * 256 + threadIdx.x) >> 5;
    int lane = threadIdx.x & 31, wl = threadIdx.x >> 5;
    if (w >= n) return;                 // uniform per warp

    int start = g_rowptr[w];
    int deg   = g_rowptr[w + 1] - start;
    float4 ad = g_dpk[2 * (size_t)w];

    // pass 1: segment max
    float4 m = make_float4(-INFINITY, -INFINITY, -INFINITY, -INFINITY);
    for (int base = 0; base < deg; base += 32) {
        int i = base + lane;
        if (i < deg) {
            float4 a = g_as4[g_csr_src[start + i]];
            m.x = fmaxf(m.x, lrelu(a.x + ad.x));
            m.y = fmaxf(m.y, lrelu(a.y + ad.y));
            m.z = fmaxf(m.z, lrelu(a.z + ad.z));
            m.w = fmaxf(m.w, lrelu(a.w + ad.w));
        }
    }
#pragma unroll
    for (int o = 16; o >= 1; o >>= 1) {
        m.x = fmaxf(m.x, __shfl_xor_sync(0xffffffffu, m.x, o));
        m.y = fmaxf(m.y, __shfl_xor_sync(0xffffffffu, m.y, o));
        m.z = fmaxf(m.z, __shfl_xor_sync(0xffffffffu, m.z, o));
        m.w = fmaxf(m.w, __shfl_xor_sync(0xffffffffu, m.w, o));
    }

    // pass 2: e = exp(l - m); denom; acc += e * xp_fp16[src]
    float4 ds = make_float4(0.f, 0.f, 0.f, 0.f);
    float accx = 0.f, accy = 0.f;
    int h = lane >> 3;                  // head of cols (2lane, 2lane+1)

    for (int base = 0; base < deg; base += 32) {
        int i = base + lane;
        int s = 0;
        float4 ev = make_float4(0.f, 0.f, 0.f, 0.f);
        if (i < deg) {
            s = g_csr_src[start + i];
            float4 a = g_as4[s];
            ev.x = expf(lrelu(a.x + ad.x) - m.x);
            ev.y = expf(lrelu(a.y + ad.y) - m.y);
            ev.z = expf(lrelu(a.z + ad.z) - m.z);
            ev.w = expf(lrelu(a.w + ad.w) - m.w);
            ds.x += ev.x; ds.y += ev.y; ds.z += ev.z; ds.w += ev.w;
        }
        sE[wl][lane][0] = ev.x; sE[wl][lane][1] = ev.y;
        sE[wl][lane][2] = ev.z; sE[wl][lane][3] = ev.w;
        __syncwarp();
        int cnt = min(32, deg - base);
        const float* sEj = &sE[wl][0][0];
#pragma unroll 4
        for (int j = 0; j < cnt; j++) {
            int sj = __shfl_sync(0xffffffffu, s, j);
            float eh = sEj[j * 4 + h];
            __half2 hv = __ldg(g_xph + (size_t)sj * 32 + lane);
            float2 f = __half22float2(hv);
            accx = fmaf(f.x, eh, accx);
            accy = fmaf(f.y, eh, accy);
        }
        __syncwarp();
    }
#pragma unroll
    for (int o = 16; o >= 1; o >>= 1) {
        ds.x += __shfl_xor_sync(0xffffffffu, ds.x, o);
        ds.y += __shfl_xor_sync(0xffffffffu, ds.y, o);
        ds.z += __shfl_xor_sync(0xffffffffu, ds.z, o);
        ds.w += __shfl_xor_sync(0xffffffffu, ds.w, o);
    }
    float4 r;
    r.x = 1.f / (ds.x + 1e-16f); r.y = 1.f / (ds.y + 1e-16f);
    r.z = 1.f / (ds.z + 1e-16f); r.w = 1.f / (ds.w + 1e-16f);
    if (lane == 0) {
        // s = rcp * exp(-m) so alpha = exp(l) * s
        g_dpk[2 * (size_t)w + 1] =
            make_float4(r.x * expf(-m.x), r.y * expf(-m.y),
                        r.z * expf(-m.z), r.w * expf(-m.w));
    }

    float rh = (lane < 8) ? r.x : (lane < 16) ? r.y : (lane < 24) ? r.z : r.w;
    float2 b2 = *(const float2*)(bias + 2 * lane);
    *(float2*)(out + (size_t)w * HC + 2 * lane) =
        make_float2(accx * rh + b2.x, accy * rh + b2.y);
}

// ---------------- alpha + edge_index copy, edge order (coalesced) ----------------
__global__ __launch_bounds__(256) void alpha_ei_kernel(
    const int* __restrict__ ei, int e,
    float* __restrict__ alpha_out, float* __restrict__ ei_out)
{
    int t = blockIdx.x * blockDim.x + threadIdx.x;
    if (t >= e) return;
    int s = ei[t], d = ei[e + t];
    if (ei_out) {
        ei_out[t]     = (float)s;
        ei_out[e + t] = (float)d;
    }
    if (alpha_out) {
        float4 a  = g_as4[s];
        float4 b  = g_dpk[2 * (size_t)d];
        float4 sc = g_dpk[2 * (size_t)d + 1];
        float4 o;
        o.x = expf(lrelu(a.x + b.x)) * sc.x;
        o.y = expf(lrelu(a.y + b.y)) * sc.y;
        o.z = expf(lrelu(a.z + b.z)) * sc.z;
        o.w = expf(lrelu(a.w + b.w)) * sc.w;
        ((float4*)alpha_out)[t] = o;
    }
}

extern "C" void kernel_launch(void* const* d_in, const int* in_sizes, int n_in,
                              void* d_out, int out_size) {
    const float* x       = (const float*)d_in[0];
    const float* W       = (const float*)d_in[1];
    const float* att_src = (const float*)d_in[2];
    const float* att_dst = (const float*)d_in[3];
    const float* bias    = (const float*)d_in[4];
    const int*   ei      = (const int*)d_in[5];
    float* out = (float*)d_out;

    int n = in_sizes[0] / IN_DIM;   // 100000
    int e = in_sizes[5] / 2;        // 1600000
    long nhc = (long)n * HC;
    int nb = (n + 511) / 512;

    init_kernel<<<(n + 511) / 512, 512>>>(n);
    gemm_kernel<<<(n + 63) / 64, 256>>>(x, W, att_src, att_dst, n);
    hist_kernel<<<((e + 3) / 4 + 255) / 256, 256>>>(ei, e);
    scan1_kernel<<<nb, 512>>>(n);
    scan2_kernel<<<1, 512>>>(nb);
    scan3_kernel<<<nb, 512>>>(n);
    fill_kernel<<<(e + 255) / 256, 256>>>(ei, e);
    aggregate_kernel<<<(n * 32 + 255) / 256, 256>>>(bias, out, n);

    float* ei_out = nullptr;
    float* alpha_out = nullptr;
    if ((long)out_size >= nhc + 2L * e)          ei_out    = out + nhc;
    if ((long)out_size >= nhc + 2L * e + 4L * e) alpha_out = out + nhc + 2L * e;

    if (ei_out || alpha_out)
        alpha_ei_kernel<<<(e + 255) / 256, 256>>>(ei, e, alpha_out, ei_out);
}